// round 17
// baseline (speedup 1.0000x reference)
#include <cuda_runtime.h>
#include <math.h>

// out[b,c,p,n,q] = sum_h C[n,h] * x[b,c,p,h,q]  for p<26,q<26 ; else 0.
// C (32x64) = (M32^3)^T[:, :26] @ (M64^3)[:26, :]   (host-computed in double)
//
// R17: lane = q. Warp owns one (bc,p): x streams global->register (1 wf/h,
// perfectly coalesced, MLP 8 per outer step), C from param const bank (LDCU,
// warp-uniform), FMA2 packed over n-pairs. No smem staging, no barriers in
// the hot path. p>=26 warps skip compute (pure zero-fill) -> 18.75% less FMA.
// Self-resetting persistent job queue (no reset kernel).

struct CtParam { float ct[64][32]; };   // ct[h][n]

#define NJOBS 1024
#define GRID  444
#define QMOD  (NJOBS + GRID)            // counter adds per launch (self-reset)

#define FMA2(d, a, b)   asm("fma.rn.f32x2 %0, %1, %2, %0;" : "+l"(d) : "l"(a), "l"(b))
#define DUP2(d, f)      asm("mov.b64 %0, {%1, %1};" : "=l"(d) : "f"(f))
#define UNPK2(lo, hi, s) asm("mov.b64 {%0, %1}, %2;" : "=f"(lo), "=f"(hi) : "l"(s))

__device__ unsigned int g_tile_ctr;     // zero-init; stays 0 mod QMOD

__global__ void __launch_bounds__(256, 3) spectral_pool_kernel(
    const float* __restrict__ x, float* __restrict__ out,
    const __grid_constant__ CtParam cp)
{
    __shared__ unsigned int sJob;

    const int tid  = threadIdx.x;
    const int w    = tid >> 5;          // warp 0..7 -> p = pg*8 + w
    const int lane = tid & 31;          // lane = q

    // C row h = 32 floats = 8 ulonglong2 (each = two f32x2 n-pairs); uniform.
    const ulonglong2* cU = reinterpret_cast<const ulonglong2*>(&cp.ct[0][0]);

    for (;;) {
        if (tid == 0) sJob = atomicAdd(&g_tile_ctr, 1u) % (unsigned)QMOD;
        __syncthreads();
        const unsigned int t = sJob;
        if (t >= NJOBS) break;

        const int bc = t >> 2;          // 0..255
        const int pg = t & 3;           // p-group of 8
        const int p  = pg * 8 + w;
        float* ob = out + (size_t)bc * 32768 + (size_t)p * 1024;

        if (p >= 26) {                  // pure zero rows: 8 x STG.128 of 0
            float4 z = make_float4(0.f, 0.f, 0.f, 0.f);
#pragma unroll
            for (int i = 0; i < 8; i++)
                __stcs(reinterpret_cast<float4*>(ob) + i * 32 + lane, z);
            continue;
        }

        const bool act = (lane < 26);   // q truncation mask
        const float* xp = x + (size_t)bc * 262144 + (size_t)p * 4096 + lane;

        unsigned long long acc[16];     // n-pairs (2i, 2i+1), f32x2
#pragma unroll
        for (int i = 0; i < 16; i++) acc[i] = 0ull;

        float xr[8], xn[8];
#pragma unroll
        for (int i = 0; i < 8; i++)
            xr[i] = act ? __ldcs(xp + (size_t)i * 64) : 0.f;

        for (int ho = 0; ho < 8; ho++) {            // 8 h-groups of 8
            if (ho < 7) {                           // batch next 8 LDG (MLP 8)
#pragma unroll
                for (int i = 0; i < 8; i++)
                    xn[i] = act ? __ldcs(xp + (size_t)((ho + 1) * 8 + i) * 64) : 0.f;
            }
#pragma unroll
            for (int k = 0; k < 8; k++) {
                unsigned long long xd;
                DUP2(xd, xr[k]);
                const ulonglong2* crow = cU + (size_t)(ho * 8 + k) * 8;
#pragma unroll
                for (int j = 0; j < 8; j++) {       // 8 x LDCU.128 (uniform)
                    ulonglong2 c2 = crow[j];
                    FMA2(acc[2 * j],     c2.x, xd);
                    FMA2(acc[2 * j + 1], c2.y, xd);
                }
            }
#pragma unroll
            for (int i = 0; i < 8; i++) xr[i] = xn[i];
        }

        // store: 32 n-rows, this lane's q column (q>=26 lanes hold exact 0)
        float* oc = ob + lane;
#pragma unroll
        for (int i = 0; i < 16; i++) {
            float lo, hi;
            UNPK2(lo, hi, acc[i]);
            __stcs(oc + (size_t)(2 * i) * 32,     lo);
            __stcs(oc + (size_t)(2 * i + 1) * 32, hi);
        }
    }
}

// ---------------- host side ----------------

static void mm_d(const double* A, const double* B, double* C, int n)
{
    for (int i = 0; i < n; i++)
        for (int j = 0; j < n; j++) {
            double s = 0.0;
            for (int k = 0; k < n; k++) s += A[i * n + k] * B[k * n + j];
            C[i * n + j] = s;
        }
}

static void build_ct(CtParam* cp)
{
    static double M64[64 * 64], T64[64 * 64], P64[64 * 64];
    static double M32[32 * 32], T32[32 * 32], P32[32 * 32];

    const double PI = 3.14159265358979323846;
    for (int k = 0; k < 64; k++)
        for (int n = 0; n < 64; n++) {
            double v = sqrt(2.0 / 64.0) * cos(PI * (2.0 * n + 1.0) * k / 128.0);
            if (k == 0) v = 1.0 / 8.0;
            M64[k * 64 + n] = v;
        }
    for (int k = 0; k < 32; k++)
        for (int n = 0; n < 32; n++) {
            double v = sqrt(2.0 / 32.0) * cos(PI * (2.0 * n + 1.0) * k / 64.0);
            if (k == 0) v = 1.0 / sqrt(32.0);
            M32[k * 32 + n] = v;
        }

    mm_d(M64, M64, T64, 64);
    mm_d(T64, M64, P64, 64);     // M64^3
    mm_d(M32, M32, T32, 32);
    mm_d(T32, M32, P32, 32);     // M32^3

    for (int n = 0; n < 32; n++)
        for (int h = 0; h < 64; h++) {
            double s = 0.0;
            for (int k = 0; k < 26; k++)
                s += P32[k * 32 + n] * P64[k * 64 + h];
            cp->ct[h][n] = (float)s;
        }
}

extern "C" void kernel_launch(void* const* d_in, const int* in_sizes, int n_in,
                              void* d_out, int out_size)
{
    (void)in_sizes; (void)n_in; (void)out_size;
    const float* x = (const float*)d_in[0];
    float* out = (float*)d_out;

    static CtParam cp;
    build_ct(&cp);

    spectral_pool_kernel<<<GRID, 256>>>(x, out, cp);
}